// round 15
// baseline (speedup 1.0000x reference)
#include <cuda_runtime.h>
#include <cuda_fp16.h>
#include <math.h>
#include <stdint.h>

#define BB    16
#define DIM   384
#define HW    56
#define WS    7
#define NWIN  (BB * 8 * 8)       // 1024
#define NTOK  49
#define ROWS  (NWIN * NTOK)      // 50176 = 16*3136
#define HEADS 12
#define HD    32
#define QKVN  (3 * DIM)          // 1152
#define SPB   3136               // spatial per batch (56*56)

// Row order is NHWC: row(b,hh,w) = (b*56+hh)*56 + w.
__device__ __align__(128) __half g_xwh [(size_t)ROWS * DIM];
__device__ __align__(128) __half g_qkvh[(size_t)ROWS * QKVN];
__device__ __align__(128) __half g_atth[(size_t)ROWS * DIM];
__device__ __align__(128) __half g_wt  [(size_t)QKVN * DIM];
__device__ __align__(128) __half g_wtp [(size_t)DIM * DIM];

// ---------------------------------------------------------------------------
// PTX helpers
// ---------------------------------------------------------------------------
__device__ __forceinline__ uint32_t smem_u32(const void* p) {
    uint32_t a;
    asm("{ .reg .u64 t; cvta.to.shared.u64 t, %1; cvt.u32.u64 %0, t; }"
        : "=r"(a) : "l"(p));
    return a;
}
__device__ __forceinline__ void cp16(uint32_t dst, const void* src) {
    asm volatile("cp.async.cg.shared.global [%0], [%1], 16;"
                 :: "r"(dst), "l"(src));
}
__device__ __forceinline__ void ldsm_x4(uint32_t* r, uint32_t addr) {
    asm volatile("ldmatrix.sync.aligned.m8n8.x4.shared.b16 {%0,%1,%2,%3}, [%4];"
                 : "=r"(r[0]), "=r"(r[1]), "=r"(r[2]), "=r"(r[3]) : "r"(addr));
}
__device__ __forceinline__ void ldsm_x2(uint32_t* r, uint32_t addr) {
    asm volatile("ldmatrix.sync.aligned.m8n8.x2.shared.b16 {%0,%1}, [%2];"
                 : "=r"(r[0]), "=r"(r[1]) : "r"(addr));
}
__device__ __forceinline__ void ldsm_x2t(uint32_t* r, uint32_t addr) {
    asm volatile("ldmatrix.sync.aligned.m8n8.x2.trans.shared.b16 {%0,%1}, [%2];"
                 : "=r"(r[0]), "=r"(r[1]) : "r"(addr));
}
__device__ __forceinline__ void mma16816(float* c, const uint32_t* a, const uint32_t* b) {
    asm volatile(
        "mma.sync.aligned.m16n8k16.row.col.f32.f16.f16.f32 "
        "{%0,%1,%2,%3}, {%4,%5,%6,%7}, {%8,%9}, {%0,%1,%2,%3};"
        : "+f"(c[0]), "+f"(c[1]), "+f"(c[2]), "+f"(c[3])
        : "r"(a[0]), "r"(a[1]), "r"(a[2]), "r"(a[3]), "r"(b[0]), "r"(b[1]));
}
__device__ __forceinline__ uint32_t pack_h2(float a, float b) {
    __half2 h = __floats2half2_rn(a, b);
    return *reinterpret_cast<uint32_t*>(&h);
}
__device__ __forceinline__ float ex2(float x) {
    float y;
    asm("ex2.approx.f32 %0, %1;" : "=f"(y) : "f"(x));
    return y;
}

// ---------------------------------------------------------------------------
// Gather: x [B, D, H, W] (f32) -> xwh [NHWC row, D] (half). Pure transpose.
// ---------------------------------------------------------------------------
__global__ __launch_bounds__(256) void gather_win(const float* __restrict__ x,
                                                  __half* __restrict__ xw) {
    __shared__ float tile[64][57];
    const int dc = blockIdx.x;
    const int hh = blockIdx.y;
    const int b  = blockIdx.z;
    const float* xp = x + (((size_t)b * DIM + dc * 64) * HW + hh) * HW;
    for (int i = threadIdx.x; i < 64 * HW; i += 256) {
        int d = i / HW, w = i % HW;
        tile[d][w] = xp[(size_t)d * HW * HW + w];
    }
    __syncthreads();
    const size_t rowbase = (size_t)(b * 56 + hh) * 56;
    for (int i = threadIdx.x; i < 32 * HW; i += 256) {
        int dp = i & 31, w = i >> 5;
        __half2 v = __floats2half2_rn(tile[dp * 2][w], tile[dp * 2 + 1][w]);
        *(__half2*)(xw + (rowbase + w) * DIM + dc * 64 + dp * 2) = v;
    }
}

// ---------------------------------------------------------------------------
// Weight transposes, fused into one launch: z=0 -> Wqkv^T, z=1 -> Wproj^T.
// ---------------------------------------------------------------------------
__global__ void transpose_w2(const float* __restrict__ W0, __half* __restrict__ Wt0,
                             const float* __restrict__ W1, __half* __restrict__ Wt1) {
    const int which = blockIdx.z;
    const int N = which ? DIM : QKVN;
    if (blockIdx.x * 32 >= N) return;
    const float* W = which ? W1 : W0;
    __half* Wt = which ? Wt1 : Wt0;
    __shared__ float t[32][33];
    int n0 = blockIdx.x * 32, k0 = blockIdx.y * 32;
    int x = threadIdx.x, y = threadIdx.y;
    for (int i = y; i < 32; i += 8)
        t[i][x] = W[(size_t)(k0 + i) * N + n0 + x];
    __syncthreads();
    for (int i = y; i < 32; i += 8)
        Wt[(size_t)(n0 + i) * DIM + k0 + x] = __float2half(t[x][i]);
}

// ---------------------------------------------------------------------------
// HGEMM (QKV): C[M,N] = A[M,K] @ Bt[N,K]^T + bias[N], half output.
// R9 optimum: 128x128 CTA, 4 warps (2x2 of 64x64), BK=64, SW128, 3-stage
// cp.async, 2 CTAs/SM, no reg cap.
// ---------------------------------------------------------------------------
#define STAGE_B 32768

template<typename OutT, int K>
__global__ __launch_bounds__(128, 2) void hgemm(const __half* __restrict__ A,
                                                const __half* __restrict__ Bt,
                                                const float* __restrict__ bias,
                                                OutT* __restrict__ C,
                                                int M, int N) {
    extern __shared__ char dsm[];
    const uint32_t sb = (smem_u32(dsm) + 1023u) & ~1023u;

    const int tid  = threadIdx.x;
    const int wid  = tid >> 5, lane = tid & 31;
    const int wm   = wid & 1;
    const int wn   = wid >> 1;

    const __half* Ap = A  + (size_t)blockIdx.y * 128 * K;
    const __half* Bp = Bt + (size_t)blockIdx.x * 128 * K;
    constexpr int NC = K >> 6;

    auto load_stage = [&](int stage, int k0) {
        const uint32_t sA = sb + stage * STAGE_B, sB = sA + 16384;
#pragma unroll
        for (int i = 0; i < 8; i++) {
            int seg = tid + 128 * i;
            int row = seg >> 3, j = seg & 7;
            uint32_t dst = (uint32_t)(row * 128 + ((j ^ (row & 7)) << 4));
            cp16(sA + dst, Ap + (size_t)row * K + k0 + j * 8);
            cp16(sB + dst, Bp + (size_t)row * K + k0 + j * 8);
        }
        asm volatile("cp.async.commit_group;" ::: "memory");
    };

    load_stage(0, 0);
    if (NC > 1) load_stage(1, 64);

    float acc[4][8][4] = {};
    const int arow = wm * 64 + (lane & 15);
    const int ac   = lane >> 4;
    const int arx  = arow & 7;
    const int brow4 = wn * 64 + ((lane >> 4) << 3) + (lane & 7);
    const int bc4   = (lane >> 3) & 1;
    const int brx4  = brow4 & 7;

#pragma unroll
    for (int c = 0; c < NC; c++) {
        if (c + 1 < NC) asm volatile("cp.async.wait_group 1;" ::: "memory");
        else            asm volatile("cp.async.wait_group 0;" ::: "memory");
        __syncthreads();
        if (c + 2 < NC) load_stage((c + 2) % 3, (c + 2) * 64);

        const uint32_t sA = sb + (c % 3) * STAGE_B, sB = sA + 16384;
#pragma unroll
        for (int ks = 0; ks < 4; ks++) {
            uint32_t af[4][4], bf[8][2];
#pragma unroll
            for (int mt = 0; mt < 4; mt++) {
                int row = arow + mt * 16;
                uint32_t addr = sA + (uint32_t)(row * 128 +
                                (((ks * 2 + ac) ^ arx) << 4));
                ldsm_x4(af[mt], addr);
            }
#pragma unroll
            for (int p = 0; p < 4; p++) {
                int row = brow4 + p * 16;
                uint32_t addr = sB + (uint32_t)(row * 128 +
                                (((ks * 2 + bc4) ^ brx4) << 4));
                uint32_t r4[4];
                ldsm_x4(r4, addr);
                bf[2 * p][0] = r4[0]; bf[2 * p][1] = r4[1];
                bf[2 * p + 1][0] = r4[2]; bf[2 * p + 1][1] = r4[3];
            }
#pragma unroll
            for (int mt = 0; mt < 4; mt++)
#pragma unroll
                for (int nt = 0; nt < 8; nt++)
                    mma16816(acc[mt][nt], af[mt], bf[nt]);
        }
    }

    const int r0 = blockIdx.y * 128 + wm * 64 + (lane >> 2);
    const int c0 = blockIdx.x * 128 + wn * 64 + (lane & 3) * 2;
#pragma unroll
    for (int mt = 0; mt < 4; mt++) {
#pragma unroll
        for (int nt = 0; nt < 8; nt++) {
            int r = r0 + mt * 16, cc = c0 + nt * 8;
            float b0 = bias[cc], b1 = bias[cc + 1];
            float v00 = acc[mt][nt][0] + b0, v01 = acc[mt][nt][1] + b1;
            float v10 = acc[mt][nt][2] + b0, v11 = acc[mt][nt][3] + b1;
            if constexpr (sizeof(OutT) == 2) {
                *(__half2*)((__half*)C + (size_t)r * N + cc)       = __floats2half2_rn(v00, v01);
                *(__half2*)((__half*)C + (size_t)(r + 8) * N + cc) = __floats2half2_rn(v10, v11);
            } else {
                *(float2*)((float*)C + (size_t)r * N + cc)       = make_float2(v00, v01);
                *(float2*)((float*)C + (size_t)(r + 8) * N + cc) = make_float2(v10, v11);
            }
        }
    }
}

// ---------------------------------------------------------------------------
// HGEMM proj + fused NCHW scatter (unchanged from R14).
// ---------------------------------------------------------------------------
__global__ __launch_bounds__(128, 2) void hgemm_proj(const __half* __restrict__ A,
                                                     const __half* __restrict__ Bt,
                                                     const float* __restrict__ bias,
                                                     float* __restrict__ out) {
    constexpr int K = DIM, N = DIM;
    extern __shared__ char dsm[];
    const uint32_t sb = (smem_u32(dsm) + 1023u) & ~1023u;

    const int tid  = threadIdx.x;
    const int wid  = tid >> 5, lane = tid & 31;
    const int wm   = wid & 1;
    const int wn   = wid >> 1;

    const __half* Ap = A  + (size_t)blockIdx.y * 128 * K;
    const __half* Bp = Bt + (size_t)blockIdx.x * 128 * K;
    constexpr int NC = K >> 6;

    auto load_stage = [&](int stage, int k0) {
        const uint32_t sA = sb + stage * STAGE_B, sB = sA + 16384;
#pragma unroll
        for (int i = 0; i < 8; i++) {
            int seg = tid + 128 * i;
            int row = seg >> 3, j = seg & 7;
            uint32_t dst = (uint32_t)(row * 128 + ((j ^ (row & 7)) << 4));
            cp16(sA + dst, Ap + (size_t)row * K + k0 + j * 8);
            cp16(sB + dst, Bp + (size_t)row * K + k0 + j * 8);
        }
        asm volatile("cp.async.commit_group;" ::: "memory");
    };

    load_stage(0, 0);
    if (NC > 1) load_stage(1, 64);

    float acc[4][8][4] = {};
    const int arow = wm * 64 + (lane & 15);
    const int ac   = lane >> 4;
    const int arx  = arow & 7;
    const int brow4 = wn * 64 + ((lane >> 4) << 3) + (lane & 7);
    const int bc4   = (lane >> 3) & 1;
    const int brx4  = brow4 & 7;

#pragma unroll
    for (int c = 0; c < NC; c++) {
        if (c + 1 < NC) asm volatile("cp.async.wait_group 1;" ::: "memory");
        else            asm volatile("cp.async.wait_group 0;" ::: "memory");
        __syncthreads();
        if (c + 2 < NC) load_stage((c + 2) % 3, (c + 2) * 64);

        const uint32_t sA = sb + (c % 3) * STAGE_B, sB = sA + 16384;
#pragma unroll
        for (int ks = 0; ks < 4; ks++) {
            uint32_t af[4][4], bf[8][2];
#pragma unroll
            for (int mt = 0; mt < 4; mt++) {
                int row = arow + mt * 16;
                uint32_t addr = sA + (uint32_t)(row * 128 +
                                (((ks * 2 + ac) ^ arx) << 4));
                ldsm_x4(af[mt], addr);
            }
#pragma unroll
            for (int p = 0; p < 4; p++) {
                int row = brow4 + p * 16;
                uint32_t addr = sB + (uint32_t)(row * 128 +
                                (((ks * 2 + bc4) ^ brx4) << 4));
                uint32_t r4[4];
                ldsm_x4(r4, addr);
                bf[2 * p][0] = r4[0]; bf[2 * p][1] = r4[1];
                bf[2 * p + 1][0] = r4[2]; bf[2 * p + 1][1] = r4[3];
            }
#pragma unroll
            for (int mt = 0; mt < 4; mt++)
#pragma unroll
                for (int nt = 0; nt < 8; nt++)
                    mma16816(acc[mt][nt], af[mt], bf[nt]);
        }
    }

    // fused scatter epilogue
    __syncthreads();
    float* tile = (float*)dsm;
    constexpr int TS = 130;
    const int rl0 = wm * 64 + (lane >> 2);
    const int cl0 = wn * 64 + (lane & 3) * 2;
    const int cg0 = blockIdx.x * 128 + cl0;
#pragma unroll
    for (int mt = 0; mt < 4; mt++) {
#pragma unroll
        for (int nt = 0; nt < 8; nt++) {
            int rl = rl0 + mt * 16, cl = cl0 + nt * 8;
            float b0 = bias[cg0 + nt * 8], b1 = bias[cg0 + nt * 8 + 1];
            *(float2*)&tile[rl * TS + cl] =
                make_float2(acc[mt][nt][0] + b0, acc[mt][nt][1] + b1);
            *(float2*)&tile[(rl + 8) * TS + cl] =
                make_float2(acc[mt][nt][2] + b0, acc[mt][nt][3] + b1);
        }
    }
    __syncthreads();
    const int R0 = blockIdx.y * 128;
    const int C0 = blockIdx.x * 128;
#pragma unroll 4
    for (int dl = 0; dl < 32; dl++) {
        int d = C0 + wid * 32 + dl;
#pragma unroll
        for (int pg = 0; pg < 4; pg++) {
            int pl = pg * 32 + lane;
            int p  = R0 + pl;
            int b  = p / SPB, rem = p % SPB;
            out[((size_t)b * DIM + d) * SPB + rem] = tile[pl * TS + wid * 32 + dl];
        }
    }
}

// ---------------------------------------------------------------------------
// Tensor-core attention: one warp per (window, head), 256 threads = 8 pairs
// per block (halved block count vs 128-thread version; same 16 warps/SM).
// ---------------------------------------------------------------------------
#define AW_ROWS  49
#define AW_MAT   (AW_ROWS * 80)
#define AW_BYTES (3 * AW_MAT)
#define AW_WARPS 8

__global__ __launch_bounds__(256) void attn_mma(const __half* __restrict__ qkv,
                                                __half* __restrict__ att) {
    extern __shared__ char sm[];
    const int warp = threadIdx.x >> 5, lane = threadIdx.x & 31;
    const int pairid = blockIdx.x * AW_WARPS + warp;
    const int win = pairid / HEADS, h = pairid % HEADS;
    const int wb = win >> 6, wh = (win >> 3) & 7, ww = win & 7;
    const size_t winbase = (size_t)wb * SPB + wh * 7 * 56 + ww * 7;

    char* smp = sm + warp * AW_BYTES;
    const uint32_t base = smem_u32(smp);
    const uint32_t sq = base, sk = base + AW_MAT, sv = base + 2 * AW_MAT;

    const __half* qp = qkv + winbase * QKVN + h * HD;

    for (int i = lane; i < 196; i += 32) {
        int t = i >> 2, seg = i & 3;
        int rowoff = (t / 7) * 56 + (t % 7);
        const __half* s0 = qp + (size_t)rowoff * QKVN + seg * 8;
        uint32_t d0 = (uint32_t)(t * 80 + seg * 16);
#pragma unroll
        for (int m = 0; m < 3; m++)
            cp16(base + m * AW_MAT + d0, s0 + m * DIM);
    }
    asm volatile("cp.async.commit_group;" ::: "memory");
    asm volatile("cp.async.wait_group 0;" ::: "memory");
    __syncwarp();

    const int r   = lane >> 2;
    const int cpr = lane & 3;

    uint32_t kb[7][2][2];
#pragma unroll
    for (int nt = 0; nt < 7; nt++)
#pragma unroll
        for (int ks = 0; ks < 2; ks++) {
            int row = nt * 8 + (lane & 7);
            if (row > 48) row = 48;
            uint32_t addr = sk + (uint32_t)(row * 80 +
                            (ks * 2 + ((lane >> 3) & 1)) * 16);
            ldsm_x2(kb[nt][ks], addr);
        }
    uint32_t vb[4][4][2];
#pragma unroll
    for (int ks = 0; ks < 4; ks++)
#pragma unroll
        for (int nd = 0; nd < 4; nd++) {
            int row = ks * 16 + (lane & 15);
            if (row > 48) row = 48;
            uint32_t addr = sv + (uint32_t)(row * 80 + nd * 16);
            ldsm_x2t(vb[ks][nd], addr);
        }

    const float CSC = 0.25506153f;  // (1/sqrt(32)) * log2(e)

#pragma unroll
    for (int mt = 0; mt < 4; mt++) {
        uint32_t qa[2][4];
        {
            int row = mt * 16 + (lane & 15);
            if (row > 48) row = 48;
#pragma unroll
            for (int ks = 0; ks < 2; ks++) {
                uint32_t addr = sq + (uint32_t)(row * 80 +
                                (ks * 2 + (lane >> 4)) * 16);
                ldsm_x4(qa[ks], addr);
            }
        }
        float s[7][4] = {};
#pragma unroll
        for (int nt = 0; nt < 7; nt++) {
            mma16816(s[nt], qa[0], kb[nt][0]);
            mma16816(s[nt], qa[1], kb[nt][1]);
        }
#pragma unroll
        for (int nt = 0; nt < 7; nt++)
#pragma unroll
            for (int j = 0; j < 4; j++) s[nt][j] *= CSC;
        if (cpr != 0) { s[6][0] = s[6][1] = s[6][2] = s[6][3] = -1e30f; }
        else          { s[6][1] = s[6][3] = -1e30f; }

        float mA = -1e30f, mB = -1e30f;
#pragma unroll
        for (int nt = 0; nt < 7; nt++) {
            mA = fmaxf(mA, fmaxf(s[nt][0], s[nt][1]));
            mB = fmaxf(mB, fmaxf(s[nt][2], s[nt][3]));
        }
        mA = fmaxf(mA, __shfl_xor_sync(0xffffffffu, mA, 1));
        mA = fmaxf(mA, __shfl_xor_sync(0xffffffffu, mA, 2));
        mB = fmaxf(mB, __shfl_xor_sync(0xffffffffu, mB, 1));
        mB = fmaxf(mB, __shfl_xor_sync(0xffffffffu, mB, 2));

        float sumA = 0.f, sumB = 0.f;
#pragma unroll
        for (int nt = 0; nt < 7; nt++) {
            s[nt][0] = ex2(s[nt][0] - mA);
            s[nt][1] = ex2(s[nt][1] - mA);
            s[nt][2] = ex2(s[nt][2] - mB);
            s[nt][3] = ex2(s[nt][3] - mB);
            sumA += s[nt][0] + s[nt][1];
            sumB += s[nt][2] + s[nt][3];
        }
        sumA += __shfl_xor_sync(0xffffffffu, sumA, 1);
        sumA += __shfl_xor_sync(0xffffffffu, sumA, 2);
        sumB += __shfl_xor_sync(0xffffffffu, sumB, 1);
        sumB += __shfl_xor_sync(0xffffffffu, sumB, 2);
        const float invA = 1.0f / sumA, invB = 1.0f / sumB;

        uint32_t pa[4][4];
#pragma unroll
        for (int ks = 0; ks < 4; ks++) {
            int nt0 = 2 * ks, nt1 = 2 * ks + 1;
            pa[ks][0] = pack_h2(s[nt0][0] * invA, s[nt0][1] * invA);
            pa[ks][1] = pack_h2(s[nt0][2] * invB, s[nt0][3] * invB);
            if (nt1 < 7) {
                pa[ks][2] = pack_h2(s[nt1][0] * invA, s[nt1][1] * invA);
                pa[ks][3] = pack_h2(s[nt1][2] * invB, s[nt1][3] * invB);
            } else {
                pa[ks][2] = 0u; pa[ks][3] = 0u;
            }
        }

        float o[4][4] = {};
#pragma unroll
        for (int ks = 0; ks < 4; ks++)
#pragma unroll
            for (int nd = 0; nd < 4; nd++)
                mma16816(o[nd], pa[ks], vb[ks][nd]);

        const int rowA = mt * 16 + r;
        const int rowB = rowA + 8;
        const size_t grA = winbase + (rowA / 7) * 56 + (rowA % 7);
        const size_t grB = winbase + (rowB / 7) * 56 + (rowB % 7);
#pragma unroll
        for (int nd = 0; nd < 4; nd++) {
            int col = h * HD + nd * 8 + cpr * 2;
            if (rowA < NTOK)
                *(__half2*)(att + grA * DIM + col) =
                    __floats2half2_rn(o[nd][0], o[nd][1]);
            if (rowB < NTOK)
                *(__half2*)(att + grB * DIM + col) =
                    __floats2half2_rn(o[nd][2], o[nd][3]);
        }
    }
}

// ---------------------------------------------------------------------------
extern "C" void kernel_launch(void* const* d_in, const int* in_sizes, int n_in,
                              void* d_out, int out_size) {
    const float* x     = (const float*)d_in[0];
    const float* Wqkv  = (const float*)d_in[1];
    const float* bqkv  = (const float*)d_in[2];
    const float* Wproj = (const float*)d_in[3];
    const float* bproj = (const float*)d_in[4];
    float* out = (float*)d_out;

    __half *xwh, *qkvh, *atth, *wt, *wtp;
    cudaGetSymbolAddress((void**)&xwh,  g_xwh);
    cudaGetSymbolAddress((void**)&qkvh, g_qkvh);
    cudaGetSymbolAddress((void**)&atth, g_atth);
    cudaGetSymbolAddress((void**)&wt,   g_wt);
    cudaGetSymbolAddress((void**)&wtp,  g_wtp);

    const int gemm_smem = 3 * STAGE_B + 1024;
    cudaFuncSetAttribute((const void*)hgemm<__half, DIM>,
                         cudaFuncAttributeMaxDynamicSharedMemorySize, gemm_smem);
    cudaFuncSetAttribute((const void*)hgemm_proj,
                         cudaFuncAttributeMaxDynamicSharedMemorySize, gemm_smem);
    const int attn_smem = AW_WARPS * AW_BYTES;   // 94080 B -> 2 blocks/SM
    cudaFuncSetAttribute(attn_mma, cudaFuncAttributeMaxDynamicSharedMemorySize, attn_smem);

    // fused weight transposes (one launch)
    transpose_w2<<<dim3(QKVN / 32, DIM / 32, 2), dim3(32, 8)>>>(Wqkv, wt, Wproj, wtp);
    gather_win<<<dim3(6, HW, BB), 256>>>(x, xwh);
    hgemm<__half, DIM><<<dim3(QKVN / 128, ROWS / 128), 128, gemm_smem>>>(
        xwh, wt, bqkv, qkvh, ROWS, QKVN);
    attn_mma<<<NWIN * HEADS / AW_WARPS, 256, attn_smem>>>(qkvh, atth);
    hgemm_proj<<<dim3(DIM / 128, ROWS / 128), 128, gemm_smem>>>(
        atth, wtp, bproj, out);
}

// round 16
// speedup vs baseline: 1.0821x; 1.0821x over previous
#include <cuda_runtime.h>
#include <cuda_fp16.h>
#include <math.h>
#include <stdint.h>

#define BB    16
#define DIM   384
#define HW    56
#define WS    7
#define NWIN  (BB * 8 * 8)       // 1024
#define NTOK  49
#define ROWS  (NWIN * NTOK)      // 50176 = 16*3136
#define HEADS 12
#define HD    32
#define QKVN  (3 * DIM)          // 1152
#define SPB   3136               // spatial per batch (56*56)

// Row order is NHWC: row(b,hh,w) = (b*56+hh)*56 + w.
__device__ __align__(128) __half g_xwh [(size_t)ROWS * DIM];
__device__ __align__(128) __half g_qkvh[(size_t)ROWS * QKVN];
__device__ __align__(128) __half g_atth[(size_t)ROWS * DIM];
__device__ __align__(128) __half g_wt  [(size_t)QKVN * DIM];
__device__ __align__(128) __half g_wtp [(size_t)DIM * DIM];

// ---------------------------------------------------------------------------
// PTX helpers
// ---------------------------------------------------------------------------
__device__ __forceinline__ uint32_t smem_u32(const void* p) {
    uint32_t a;
    asm("{ .reg .u64 t; cvta.to.shared.u64 t, %1; cvt.u32.u64 %0, t; }"
        : "=r"(a) : "l"(p));
    return a;
}
__device__ __forceinline__ void cp16(uint32_t dst, const void* src) {
    asm volatile("cp.async.cg.shared.global [%0], [%1], 16;"
                 :: "r"(dst), "l"(src));
}
__device__ __forceinline__ void ldsm_x4(uint32_t* r, uint32_t addr) {
    asm volatile("ldmatrix.sync.aligned.m8n8.x4.shared.b16 {%0,%1,%2,%3}, [%4];"
                 : "=r"(r[0]), "=r"(r[1]), "=r"(r[2]), "=r"(r[3]) : "r"(addr));
}
__device__ __forceinline__ void ldsm_x2(uint32_t* r, uint32_t addr) {
    asm volatile("ldmatrix.sync.aligned.m8n8.x2.shared.b16 {%0,%1}, [%2];"
                 : "=r"(r[0]), "=r"(r[1]) : "r"(addr));
}
__device__ __forceinline__ void ldsm_x2t(uint32_t* r, uint32_t addr) {
    asm volatile("ldmatrix.sync.aligned.m8n8.x2.trans.shared.b16 {%0,%1}, [%2];"
                 : "=r"(r[0]), "=r"(r[1]) : "r"(addr));
}
__device__ __forceinline__ void mma16816(float* c, const uint32_t* a, const uint32_t* b) {
    asm volatile(
        "mma.sync.aligned.m16n8k16.row.col.f32.f16.f16.f32 "
        "{%0,%1,%2,%3}, {%4,%5,%6,%7}, {%8,%9}, {%0,%1,%2,%3};"
        : "+f"(c[0]), "+f"(c[1]), "+f"(c[2]), "+f"(c[3])
        : "r"(a[0]), "r"(a[1]), "r"(a[2]), "r"(a[3]), "r"(b[0]), "r"(b[1]));
}
__device__ __forceinline__ uint32_t pack_h2(float a, float b) {
    __half2 h = __floats2half2_rn(a, b);
    return *reinterpret_cast<uint32_t*>(&h);
}
__device__ __forceinline__ float ex2(float x) {
    float y;
    asm("ex2.approx.f32 %0, %1;" : "=f"(y) : "f"(x));
    return y;
}

// ---------------------------------------------------------------------------
// Gather: x [B, D, H, W] (f32) -> xwh [NHWC row, D] (half). Pure transpose.
// ---------------------------------------------------------------------------
__global__ __launch_bounds__(256) void gather_win(const float* __restrict__ x,
                                                  __half* __restrict__ xw) {
    __shared__ float tile[64][57];
    const int dc = blockIdx.x;
    const int hh = blockIdx.y;
    const int b  = blockIdx.z;
    const float* xp = x + (((size_t)b * DIM + dc * 64) * HW + hh) * HW;
    for (int i = threadIdx.x; i < 64 * HW; i += 256) {
        int d = i / HW, w = i % HW;
        tile[d][w] = xp[(size_t)d * HW * HW + w];
    }
    __syncthreads();
    const size_t rowbase = (size_t)(b * 56 + hh) * 56;
    for (int i = threadIdx.x; i < 32 * HW; i += 256) {
        int dp = i & 31, w = i >> 5;
        __half2 v = __floats2half2_rn(tile[dp * 2][w], tile[dp * 2 + 1][w]);
        *(__half2*)(xw + (rowbase + w) * DIM + dc * 64 + dp * 2) = v;
    }
}

// ---------------------------------------------------------------------------
// Weight transposes, fused into one launch: z=0 -> Wqkv^T, z=1 -> Wproj^T.
// ---------------------------------------------------------------------------
__global__ void transpose_w2(const float* __restrict__ W0, __half* __restrict__ Wt0,
                             const float* __restrict__ W1, __half* __restrict__ Wt1) {
    const int which = blockIdx.z;
    const int N = which ? DIM : QKVN;
    if (blockIdx.x * 32 >= N) return;
    const float* W = which ? W1 : W0;
    __half* Wt = which ? Wt1 : Wt0;
    __shared__ float t[32][33];
    int n0 = blockIdx.x * 32, k0 = blockIdx.y * 32;
    int x = threadIdx.x, y = threadIdx.y;
    for (int i = y; i < 32; i += 8)
        t[i][x] = W[(size_t)(k0 + i) * N + n0 + x];
    __syncthreads();
    for (int i = y; i < 32; i += 8)
        Wt[(size_t)(n0 + i) * DIM + k0 + x] = __float2half(t[x][i]);
}

// ---------------------------------------------------------------------------
// HGEMM (QKV): C[M,N] = A[M,K] @ Bt[N,K]^T + bias[N], half output.
// R9 optimum: 128x128 CTA, 4 warps (2x2 of 64x64), BK=64, SW128, 3-stage
// cp.async, 2 CTAs/SM, no reg cap.
// ---------------------------------------------------------------------------
#define STAGE_B 32768

template<typename OutT, int K>
__global__ __launch_bounds__(128, 2) void hgemm(const __half* __restrict__ A,
                                                const __half* __restrict__ Bt,
                                                const float* __restrict__ bias,
                                                OutT* __restrict__ C,
                                                int M, int N) {
    extern __shared__ char dsm[];
    const uint32_t sb = (smem_u32(dsm) + 1023u) & ~1023u;

    const int tid  = threadIdx.x;
    const int wid  = tid >> 5, lane = tid & 31;
    const int wm   = wid & 1;
    const int wn   = wid >> 1;

    const __half* Ap = A  + (size_t)blockIdx.y * 128 * K;
    const __half* Bp = Bt + (size_t)blockIdx.x * 128 * K;
    constexpr int NC = K >> 6;

    auto load_stage = [&](int stage, int k0) {
        const uint32_t sA = sb + stage * STAGE_B, sB = sA + 16384;
#pragma unroll
        for (int i = 0; i < 8; i++) {
            int seg = tid + 128 * i;
            int row = seg >> 3, j = seg & 7;
            uint32_t dst = (uint32_t)(row * 128 + ((j ^ (row & 7)) << 4));
            cp16(sA + dst, Ap + (size_t)row * K + k0 + j * 8);
            cp16(sB + dst, Bp + (size_t)row * K + k0 + j * 8);
        }
        asm volatile("cp.async.commit_group;" ::: "memory");
    };

    load_stage(0, 0);
    if (NC > 1) load_stage(1, 64);

    float acc[4][8][4] = {};
    const int arow = wm * 64 + (lane & 15);
    const int ac   = lane >> 4;
    const int arx  = arow & 7;
    const int brow4 = wn * 64 + ((lane >> 4) << 3) + (lane & 7);
    const int bc4   = (lane >> 3) & 1;
    const int brx4  = brow4 & 7;

#pragma unroll
    for (int c = 0; c < NC; c++) {
        if (c + 1 < NC) asm volatile("cp.async.wait_group 1;" ::: "memory");
        else            asm volatile("cp.async.wait_group 0;" ::: "memory");
        __syncthreads();
        if (c + 2 < NC) load_stage((c + 2) % 3, (c + 2) * 64);

        const uint32_t sA = sb + (c % 3) * STAGE_B, sB = sA + 16384;
#pragma unroll
        for (int ks = 0; ks < 4; ks++) {
            uint32_t af[4][4], bf[8][2];
#pragma unroll
            for (int mt = 0; mt < 4; mt++) {
                int row = arow + mt * 16;
                uint32_t addr = sA + (uint32_t)(row * 128 +
                                (((ks * 2 + ac) ^ arx) << 4));
                ldsm_x4(af[mt], addr);
            }
#pragma unroll
            for (int p = 0; p < 4; p++) {
                int row = brow4 + p * 16;
                uint32_t addr = sB + (uint32_t)(row * 128 +
                                (((ks * 2 + bc4) ^ brx4) << 4));
                uint32_t r4[4];
                ldsm_x4(r4, addr);
                bf[2 * p][0] = r4[0]; bf[2 * p][1] = r4[1];
                bf[2 * p + 1][0] = r4[2]; bf[2 * p + 1][1] = r4[3];
            }
#pragma unroll
            for (int mt = 0; mt < 4; mt++)
#pragma unroll
                for (int nt = 0; nt < 8; nt++)
                    mma16816(acc[mt][nt], af[mt], bf[nt]);
        }
    }

    const int r0 = blockIdx.y * 128 + wm * 64 + (lane >> 2);
    const int c0 = blockIdx.x * 128 + wn * 64 + (lane & 3) * 2;
#pragma unroll
    for (int mt = 0; mt < 4; mt++) {
#pragma unroll
        for (int nt = 0; nt < 8; nt++) {
            int r = r0 + mt * 16, cc = c0 + nt * 8;
            float b0 = bias[cc], b1 = bias[cc + 1];
            float v00 = acc[mt][nt][0] + b0, v01 = acc[mt][nt][1] + b1;
            float v10 = acc[mt][nt][2] + b0, v11 = acc[mt][nt][3] + b1;
            if constexpr (sizeof(OutT) == 2) {
                *(__half2*)((__half*)C + (size_t)r * N + cc)       = __floats2half2_rn(v00, v01);
                *(__half2*)((__half*)C + (size_t)(r + 8) * N + cc) = __floats2half2_rn(v10, v11);
            } else {
                *(float2*)((float*)C + (size_t)r * N + cc)       = make_float2(v00, v01);
                *(float2*)((float*)C + (size_t)(r + 8) * N + cc) = make_float2(v10, v11);
            }
        }
    }
}

// ---------------------------------------------------------------------------
// HGEMM proj + fused NCHW scatter (unchanged from R14).
// ---------------------------------------------------------------------------
__global__ __launch_bounds__(128, 2) void hgemm_proj(const __half* __restrict__ A,
                                                     const __half* __restrict__ Bt,
                                                     const float* __restrict__ bias,
                                                     float* __restrict__ out) {
    constexpr int K = DIM, N = DIM;
    extern __shared__ char dsm[];
    const uint32_t sb = (smem_u32(dsm) + 1023u) & ~1023u;

    const int tid  = threadIdx.x;
    const int wid  = tid >> 5, lane = tid & 31;
    const int wm   = wid & 1;
    const int wn   = wid >> 1;

    const __half* Ap = A  + (size_t)blockIdx.y * 128 * K;
    const __half* Bp = Bt + (size_t)blockIdx.x * 128 * K;
    constexpr int NC = K >> 6;

    auto load_stage = [&](int stage, int k0) {
        const uint32_t sA = sb + stage * STAGE_B, sB = sA + 16384;
#pragma unroll
        for (int i = 0; i < 8; i++) {
            int seg = tid + 128 * i;
            int row = seg >> 3, j = seg & 7;
            uint32_t dst = (uint32_t)(row * 128 + ((j ^ (row & 7)) << 4));
            cp16(sA + dst, Ap + (size_t)row * K + k0 + j * 8);
            cp16(sB + dst, Bp + (size_t)row * K + k0 + j * 8);
        }
        asm volatile("cp.async.commit_group;" ::: "memory");
    };

    load_stage(0, 0);
    if (NC > 1) load_stage(1, 64);

    float acc[4][8][4] = {};
    const int arow = wm * 64 + (lane & 15);
    const int ac   = lane >> 4;
    const int arx  = arow & 7;
    const int brow4 = wn * 64 + ((lane >> 4) << 3) + (lane & 7);
    const int bc4   = (lane >> 3) & 1;
    const int brx4  = brow4 & 7;

#pragma unroll
    for (int c = 0; c < NC; c++) {
        if (c + 1 < NC) asm volatile("cp.async.wait_group 1;" ::: "memory");
        else            asm volatile("cp.async.wait_group 0;" ::: "memory");
        __syncthreads();
        if (c + 2 < NC) load_stage((c + 2) % 3, (c + 2) * 64);

        const uint32_t sA = sb + (c % 3) * STAGE_B, sB = sA + 16384;
#pragma unroll
        for (int ks = 0; ks < 4; ks++) {
            uint32_t af[4][4], bf[8][2];
#pragma unroll
            for (int mt = 0; mt < 4; mt++) {
                int row = arow + mt * 16;
                uint32_t addr = sA + (uint32_t)(row * 128 +
                                (((ks * 2 + ac) ^ arx) << 4));
                ldsm_x4(af[mt], addr);
            }
#pragma unroll
            for (int p = 0; p < 4; p++) {
                int row = brow4 + p * 16;
                uint32_t addr = sB + (uint32_t)(row * 128 +
                                (((ks * 2 + bc4) ^ brx4) << 4));
                uint32_t r4[4];
                ldsm_x4(r4, addr);
                bf[2 * p][0] = r4[0]; bf[2 * p][1] = r4[1];
                bf[2 * p + 1][0] = r4[2]; bf[2 * p + 1][1] = r4[3];
            }
#pragma unroll
            for (int mt = 0; mt < 4; mt++)
#pragma unroll
                for (int nt = 0; nt < 8; nt++)
                    mma16816(acc[mt][nt], af[mt], bf[nt]);
        }
    }

    // fused scatter epilogue
    __syncthreads();
    float* tile = (float*)dsm;
    constexpr int TS = 130;
    const int rl0 = wm * 64 + (lane >> 2);
    const int cl0 = wn * 64 + (lane & 3) * 2;
    const int cg0 = blockIdx.x * 128 + cl0;
#pragma unroll
    for (int mt = 0; mt < 4; mt++) {
#pragma unroll
        for (int nt = 0; nt < 8; nt++) {
            int rl = rl0 + mt * 16, cl = cl0 + nt * 8;
            float b0 = bias[cg0 + nt * 8], b1 = bias[cg0 + nt * 8 + 1];
            *(float2*)&tile[rl * TS + cl] =
                make_float2(acc[mt][nt][0] + b0, acc[mt][nt][1] + b1);
            *(float2*)&tile[(rl + 8) * TS + cl] =
                make_float2(acc[mt][nt][2] + b0, acc[mt][nt][3] + b1);
        }
    }
    __syncthreads();
    const int R0 = blockIdx.y * 128;
    const int C0 = blockIdx.x * 128;
#pragma unroll 4
    for (int dl = 0; dl < 32; dl++) {
        int d = C0 + wid * 32 + dl;
#pragma unroll
        for (int pg = 0; pg < 4; pg++) {
            int pl = pg * 32 + lane;
            int p  = R0 + pl;
            int b  = p / SPB, rem = p % SPB;
            out[((size_t)b * DIM + d) * SPB + rem] = tile[pl * TS + wid * 32 + dl];
        }
    }
}

// ---------------------------------------------------------------------------
// Tensor-core attention: one warp per (window, head), 128 threads = 4 pairs
// per block. V fragments loaded per-mt (not hoisted) to keep regs < 128 so
// FOUR blocks co-reside (16 warps/SM); attn is memory-bound and needs warps.
// ---------------------------------------------------------------------------
#define AW_ROWS  49
#define AW_MAT   (AW_ROWS * 80)
#define AW_BYTES (3 * AW_MAT)
#define AW_WARPS 4

__global__ __launch_bounds__(128, 4) void attn_mma(const __half* __restrict__ qkv,
                                                   __half* __restrict__ att) {
    extern __shared__ char sm[];
    const int warp = threadIdx.x >> 5, lane = threadIdx.x & 31;
    const int pairid = blockIdx.x * AW_WARPS + warp;
    const int win = pairid / HEADS, h = pairid % HEADS;
    const int wb = win >> 6, wh = (win >> 3) & 7, ww = win & 7;
    const size_t winbase = (size_t)wb * SPB + wh * 7 * 56 + ww * 7;

    char* smp = sm + warp * AW_BYTES;
    const uint32_t base = smem_u32(smp);
    const uint32_t sq = base, sk = base + AW_MAT, sv = base + 2 * AW_MAT;

    const __half* qp = qkv + winbase * QKVN + h * HD;

    for (int i = lane; i < 196; i += 32) {
        int t = i >> 2, seg = i & 3;
        int rowoff = (t / 7) * 56 + (t % 7);
        const __half* s0 = qp + (size_t)rowoff * QKVN + seg * 8;
        uint32_t d0 = (uint32_t)(t * 80 + seg * 16);
#pragma unroll
        for (int m = 0; m < 3; m++)
            cp16(base + m * AW_MAT + d0, s0 + m * DIM);
    }
    asm volatile("cp.async.commit_group;" ::: "memory");
    asm volatile("cp.async.wait_group 0;" ::: "memory");
    __syncwarp();

    const int r   = lane >> 2;
    const int cpr = lane & 3;

    // K fragments hoisted (28 regs); rows clamped <=48
    uint32_t kb[7][2][2];
#pragma unroll
    for (int nt = 0; nt < 7; nt++)
#pragma unroll
        for (int ks = 0; ks < 2; ks++) {
            int row = nt * 8 + (lane & 7);
            if (row > 48) row = 48;
            uint32_t addr = sk + (uint32_t)(row * 80 +
                            (ks * 2 + ((lane >> 3) & 1)) * 16);
            ldsm_x2(kb[nt][ks], addr);
        }

    const float CSC = 0.25506153f;  // (1/sqrt(32)) * log2(e)
    const int vrow_base = lane & 15;

#pragma unroll
    for (int mt = 0; mt < 4; mt++) {
        uint32_t qa[2][4];
        {
            int row = mt * 16 + (lane & 15);
            if (row > 48) row = 48;
#pragma unroll
            for (int ks = 0; ks < 2; ks++) {
                uint32_t addr = sq + (uint32_t)(row * 80 +
                                (ks * 2 + (lane >> 4)) * 16);
                ldsm_x4(qa[ks], addr);
            }
        }
        float s[7][4] = {};
#pragma unroll
        for (int nt = 0; nt < 7; nt++) {
            mma16816(s[nt], qa[0], kb[nt][0]);
            mma16816(s[nt], qa[1], kb[nt][1]);
        }
#pragma unroll
        for (int nt = 0; nt < 7; nt++)
#pragma unroll
            for (int j = 0; j < 4; j++) s[nt][j] *= CSC;
        if (cpr != 0) { s[6][0] = s[6][1] = s[6][2] = s[6][3] = -1e30f; }
        else          { s[6][1] = s[6][3] = -1e30f; }

        float mA = -1e30f, mB = -1e30f;
#pragma unroll
        for (int nt = 0; nt < 7; nt++) {
            mA = fmaxf(mA, fmaxf(s[nt][0], s[nt][1]));
            mB = fmaxf(mB, fmaxf(s[nt][2], s[nt][3]));
        }
        mA = fmaxf(mA, __shfl_xor_sync(0xffffffffu, mA, 1));
        mA = fmaxf(mA, __shfl_xor_sync(0xffffffffu, mA, 2));
        mB = fmaxf(mB, __shfl_xor_sync(0xffffffffu, mB, 1));
        mB = fmaxf(mB, __shfl_xor_sync(0xffffffffu, mB, 2));

        float sumA = 0.f, sumB = 0.f;
#pragma unroll
        for (int nt = 0; nt < 7; nt++) {
            s[nt][0] = ex2(s[nt][0] - mA);
            s[nt][1] = ex2(s[nt][1] - mA);
            s[nt][2] = ex2(s[nt][2] - mB);
            s[nt][3] = ex2(s[nt][3] - mB);
            sumA += s[nt][0] + s[nt][1];
            sumB += s[nt][2] + s[nt][3];
        }
        sumA += __shfl_xor_sync(0xffffffffu, sumA, 1);
        sumA += __shfl_xor_sync(0xffffffffu, sumA, 2);
        sumB += __shfl_xor_sync(0xffffffffu, sumB, 1);
        sumB += __shfl_xor_sync(0xffffffffu, sumB, 2);
        const float invA = 1.0f / sumA, invB = 1.0f / sumB;

        uint32_t pa[4][4];
#pragma unroll
        for (int ks = 0; ks < 4; ks++) {
            int nt0 = 2 * ks, nt1 = 2 * ks + 1;
            pa[ks][0] = pack_h2(s[nt0][0] * invA, s[nt0][1] * invA);
            pa[ks][1] = pack_h2(s[nt0][2] * invB, s[nt0][3] * invB);
            if (nt1 < 7) {
                pa[ks][2] = pack_h2(s[nt1][0] * invA, s[nt1][1] * invA);
                pa[ks][3] = pack_h2(s[nt1][2] * invB, s[nt1][3] * invB);
            } else {
                pa[ks][2] = 0u; pa[ks][3] = 0u;
            }
        }

        // P @ V with V fragments loaded in-loop (saves 32 registers)
        float o[4][4] = {};
#pragma unroll
        for (int ks = 0; ks < 4; ks++) {
            int vrow = ks * 16 + vrow_base;
            if (vrow > 48) vrow = 48;
#pragma unroll
            for (int nd = 0; nd < 4; nd++) {
                uint32_t vbf[2];
                ldsm_x2t(vbf, sv + (uint32_t)(vrow * 80 + nd * 16));
                mma16816(o[nd], pa[ks], vbf);
            }
        }

        const int rowA = mt * 16 + r;
        const int rowB = rowA + 8;
        const size_t grA = winbase + (rowA / 7) * 56 + (rowA % 7);
        const size_t grB = winbase + (rowB / 7) * 56 + (rowB % 7);
#pragma unroll
        for (int nd = 0; nd < 4; nd++) {
            int col = h * HD + nd * 8 + cpr * 2;
            if (rowA < NTOK)
                *(__half2*)(att + grA * DIM + col) =
                    __floats2half2_rn(o[nd][0], o[nd][1]);
            if (rowB < NTOK)
                *(__half2*)(att + grB * DIM + col) =
                    __floats2half2_rn(o[nd][2], o[nd][3]);
        }
    }
}

// ---------------------------------------------------------------------------
extern "C" void kernel_launch(void* const* d_in, const int* in_sizes, int n_in,
                              void* d_out, int out_size) {
    const float* x     = (const float*)d_in[0];
    const float* Wqkv  = (const float*)d_in[1];
    const float* bqkv  = (const float*)d_in[2];
    const float* Wproj = (const float*)d_in[3];
    const float* bproj = (const float*)d_in[4];
    float* out = (float*)d_out;

    __half *xwh, *qkvh, *atth, *wt, *wtp;
    cudaGetSymbolAddress((void**)&xwh,  g_xwh);
    cudaGetSymbolAddress((void**)&qkvh, g_qkvh);
    cudaGetSymbolAddress((void**)&atth, g_atth);
    cudaGetSymbolAddress((void**)&wt,   g_wt);
    cudaGetSymbolAddress((void**)&wtp,  g_wtp);

    const int gemm_smem = 3 * STAGE_B + 1024;
    cudaFuncSetAttribute((const void*)hgemm<__half, DIM>,
                         cudaFuncAttributeMaxDynamicSharedMemorySize, gemm_smem);
    cudaFuncSetAttribute((const void*)hgemm_proj,
                         cudaFuncAttributeMaxDynamicSharedMemorySize, gemm_smem);
    const int attn_smem = AW_WARPS * AW_BYTES;   // 47040 B -> 4 blocks/SM
    cudaFuncSetAttribute(attn_mma, cudaFuncAttributeMaxDynamicSharedMemorySize, attn_smem);

    transpose_w2<<<dim3(QKVN / 32, DIM / 32, 2), dim3(32, 8)>>>(Wqkv, wt, Wproj, wtp);
    gather_win<<<dim3(6, HW, BB), 256>>>(x, xwh);
    hgemm<__half, DIM><<<dim3(QKVN / 128, ROWS / 128), 128, gemm_smem>>>(
        xwh, wt, bqkv, qkvh, ROWS, QKVN);
    attn_mma<<<NWIN * HEADS / AW_WARPS, 128, attn_smem>>>(qkvh, atth);
    hgemm_proj<<<dim3(DIM / 128, ROWS / 128), 128, gemm_smem>>>(
        atth, wtp, bproj, out);
}

// round 17
// speedup vs baseline: 1.2066x; 1.1151x over previous
#include <cuda_runtime.h>
#include <cuda_fp16.h>
#include <math.h>
#include <stdint.h>

#define BB    16
#define DIM   384
#define HW    56
#define WS    7
#define NWIN  (BB * 8 * 8)       // 1024
#define NTOK  49
#define ROWS  (NWIN * NTOK)      // 50176 = 16*3136
#define HEADS 12
#define HD    32
#define QKVN  (3 * DIM)          // 1152
#define SPB   3136               // spatial per batch (56*56)

// Row order is NHWC: row(b,hh,w) = (b*56+hh)*56 + w.
__device__ __align__(128) __half g_xwh [(size_t)ROWS * DIM];
__device__ __align__(128) __half g_qkvh[(size_t)ROWS * QKVN];
__device__ __align__(128) __half g_atth[(size_t)ROWS * DIM];
__device__ __align__(128) __half g_wt  [(size_t)QKVN * DIM];
__device__ __align__(128) __half g_wtp [(size_t)DIM * DIM];

// ---------------------------------------------------------------------------
// PTX helpers
// ---------------------------------------------------------------------------
__device__ __forceinline__ uint32_t smem_u32(const void* p) {
    uint32_t a;
    asm("{ .reg .u64 t; cvta.to.shared.u64 t, %1; cvt.u32.u64 %0, t; }"
        : "=r"(a) : "l"(p));
    return a;
}
__device__ __forceinline__ void cp16(uint32_t dst, const void* src) {
    asm volatile("cp.async.cg.shared.global [%0], [%1], 16;"
                 :: "r"(dst), "l"(src));
}
__device__ __forceinline__ void ldsm_x4(uint32_t* r, uint32_t addr) {
    asm volatile("ldmatrix.sync.aligned.m8n8.x4.shared.b16 {%0,%1,%2,%3}, [%4];"
                 : "=r"(r[0]), "=r"(r[1]), "=r"(r[2]), "=r"(r[3]) : "r"(addr));
}
__device__ __forceinline__ void ldsm_x2(uint32_t* r, uint32_t addr) {
    asm volatile("ldmatrix.sync.aligned.m8n8.x2.shared.b16 {%0,%1}, [%2];"
                 : "=r"(r[0]), "=r"(r[1]) : "r"(addr));
}
__device__ __forceinline__ void ldsm_x2t(uint32_t* r, uint32_t addr) {
    asm volatile("ldmatrix.sync.aligned.m8n8.x2.trans.shared.b16 {%0,%1}, [%2];"
                 : "=r"(r[0]), "=r"(r[1]) : "r"(addr));
}
__device__ __forceinline__ void mma16816(float* c, const uint32_t* a, const uint32_t* b) {
    asm volatile(
        "mma.sync.aligned.m16n8k16.row.col.f32.f16.f16.f32 "
        "{%0,%1,%2,%3}, {%4,%5,%6,%7}, {%8,%9}, {%0,%1,%2,%3};"
        : "+f"(c[0]), "+f"(c[1]), "+f"(c[2]), "+f"(c[3])
        : "r"(a[0]), "r"(a[1]), "r"(a[2]), "r"(a[3]), "r"(b[0]), "r"(b[1]));
}
__device__ __forceinline__ uint32_t pack_h2(float a, float b) {
    __half2 h = __floats2half2_rn(a, b);
    return *reinterpret_cast<uint32_t*>(&h);
}
__device__ __forceinline__ float ex2(float x) {
    float y;
    asm("ex2.approx.f32 %0, %1;" : "=f"(y) : "f"(x));
    return y;
}

// ---------------------------------------------------------------------------
// prep: merged gather + weight transposes.
// z in [0,BB): gather slice (x NCHW f32 -> xwh NHWC half), float4 loads.
// z in [BB, BB+2): weight-transpose tiles (Wqkv->wt, Wproj->wtp).
// ---------------------------------------------------------------------------
__global__ __launch_bounds__(256) void prep(const float* __restrict__ x,
                                            __half* __restrict__ xw,
                                            const float* __restrict__ Wqkv,
                                            __half* __restrict__ wt,
                                            const float* __restrict__ Wproj,
                                            __half* __restrict__ wtp) {
    __shared__ float tile[64][57];
    const int tid = threadIdx.x;

    if (blockIdx.z < BB) {
        // ---- gather ----
        const int dc = blockIdx.x;      // 0..5
        const int hh = blockIdx.y;      // 0..55
        const int b  = blockIdx.z;      // 0..15
        const float* xp = x + (((size_t)b * DIM + dc * 64) * HW + hh) * HW;
        for (int i = tid; i < 64 * 14; i += 256) {     // float4 loads (56 = 14*4)
            int d = i / 14, w4 = i % 14;
            float4 v = *(const float4*)(xp + (size_t)d * HW * HW + w4 * 4);
            tile[d][w4 * 4 + 0] = v.x;
            tile[d][w4 * 4 + 1] = v.y;
            tile[d][w4 * 4 + 2] = v.z;
            tile[d][w4 * 4 + 3] = v.w;
        }
        __syncthreads();
        const size_t rowbase = (size_t)(b * 56 + hh) * 56;
        for (int i = tid; i < 32 * HW; i += 256) {
            int dp = i & 31, w = i >> 5;
            __half2 v = __floats2half2_rn(tile[dp * 2][w], tile[dp * 2 + 1][w]);
            *(__half2*)(xw + (rowbase + w) * DIM + dc * 64 + dp * 2) = v;
        }
    } else {
        // ---- weight transposes ----
        int lin = (blockIdx.z - BB) * (6 * HW) + blockIdx.y * 6 + blockIdx.x;
        const int NQ_TILES = (QKVN / 32) * (DIM / 32);   // 432
        const int NP_TILES = (DIM / 32) * (DIM / 32);    // 144
        if (lin >= NQ_TILES + NP_TILES) return;
        const float* W; __half* Wt; int N, n0, k0;
        if (lin < NQ_TILES) {
            W = Wqkv; Wt = wt; N = QKVN;
            n0 = (lin % (QKVN / 32)) * 32; k0 = (lin / (QKVN / 32)) * 32;
        } else {
            lin -= NQ_TILES;
            W = Wproj; Wt = wtp; N = DIM;
            n0 = (lin % (DIM / 32)) * 32; k0 = (lin / (DIM / 32)) * 32;
        }
        float (*t)[57] = tile;   // reuse smem (only need 32x33)
        int xi = tid & 31, yi = tid >> 5;
        for (int i = yi; i < 32; i += 8)
            t[i][xi] = W[(size_t)(k0 + i) * N + n0 + xi];
        __syncthreads();
        for (int i = yi; i < 32; i += 8)
            Wt[(size_t)(n0 + i) * DIM + k0 + xi] = __float2half(t[xi][i]);
    }
}

// ---------------------------------------------------------------------------
// HGEMM (QKV): C[M,N] = A[M,K] @ Bt[N,K]^T + bias[N], half output.
// R9 optimum: 128x128 CTA, 4 warps (2x2 of 64x64), BK=64, SW128, 3-stage
// cp.async, 2 CTAs/SM, no reg cap. UNCHANGED.
// ---------------------------------------------------------------------------
#define STAGE_B 32768

template<typename OutT, int K>
__global__ __launch_bounds__(128, 2) void hgemm(const __half* __restrict__ A,
                                                const __half* __restrict__ Bt,
                                                const float* __restrict__ bias,
                                                OutT* __restrict__ C,
                                                int M, int N) {
    extern __shared__ char dsm[];
    const uint32_t sb = (smem_u32(dsm) + 1023u) & ~1023u;

    const int tid  = threadIdx.x;
    const int wid  = tid >> 5, lane = tid & 31;
    const int wm   = wid & 1;
    const int wn   = wid >> 1;

    const __half* Ap = A  + (size_t)blockIdx.y * 128 * K;
    const __half* Bp = Bt + (size_t)blockIdx.x * 128 * K;
    constexpr int NC = K >> 6;

    auto load_stage = [&](int stage, int k0) {
        const uint32_t sA = sb + stage * STAGE_B, sB = sA + 16384;
#pragma unroll
        for (int i = 0; i < 8; i++) {
            int seg = tid + 128 * i;
            int row = seg >> 3, j = seg & 7;
            uint32_t dst = (uint32_t)(row * 128 + ((j ^ (row & 7)) << 4));
            cp16(sA + dst, Ap + (size_t)row * K + k0 + j * 8);
            cp16(sB + dst, Bp + (size_t)row * K + k0 + j * 8);
        }
        asm volatile("cp.async.commit_group;" ::: "memory");
    };

    load_stage(0, 0);
    if (NC > 1) load_stage(1, 64);

    float acc[4][8][4] = {};
    const int arow = wm * 64 + (lane & 15);
    const int ac   = lane >> 4;
    const int arx  = arow & 7;
    const int brow4 = wn * 64 + ((lane >> 4) << 3) + (lane & 7);
    const int bc4   = (lane >> 3) & 1;
    const int brx4  = brow4 & 7;

#pragma unroll
    for (int c = 0; c < NC; c++) {
        if (c + 1 < NC) asm volatile("cp.async.wait_group 1;" ::: "memory");
        else            asm volatile("cp.async.wait_group 0;" ::: "memory");
        __syncthreads();
        if (c + 2 < NC) load_stage((c + 2) % 3, (c + 2) * 64);

        const uint32_t sA = sb + (c % 3) * STAGE_B, sB = sA + 16384;
#pragma unroll
        for (int ks = 0; ks < 4; ks++) {
            uint32_t af[4][4], bf[8][2];
#pragma unroll
            for (int mt = 0; mt < 4; mt++) {
                int row = arow + mt * 16;
                uint32_t addr = sA + (uint32_t)(row * 128 +
                                (((ks * 2 + ac) ^ arx) << 4));
                ldsm_x4(af[mt], addr);
            }
#pragma unroll
            for (int p = 0; p < 4; p++) {
                int row = brow4 + p * 16;
                uint32_t addr = sB + (uint32_t)(row * 128 +
                                (((ks * 2 + bc4) ^ brx4) << 4));
                uint32_t r4[4];
                ldsm_x4(r4, addr);
                bf[2 * p][0] = r4[0]; bf[2 * p][1] = r4[1];
                bf[2 * p + 1][0] = r4[2]; bf[2 * p + 1][1] = r4[3];
            }
#pragma unroll
            for (int mt = 0; mt < 4; mt++)
#pragma unroll
                for (int nt = 0; nt < 8; nt++)
                    mma16816(acc[mt][nt], af[mt], bf[nt]);
        }
    }

    const int r0 = blockIdx.y * 128 + wm * 64 + (lane >> 2);
    const int c0 = blockIdx.x * 128 + wn * 64 + (lane & 3) * 2;
#pragma unroll
    for (int mt = 0; mt < 4; mt++) {
#pragma unroll
        for (int nt = 0; nt < 8; nt++) {
            int r = r0 + mt * 16, cc = c0 + nt * 8;
            float b0 = bias[cc], b1 = bias[cc + 1];
            float v00 = acc[mt][nt][0] + b0, v01 = acc[mt][nt][1] + b1;
            float v10 = acc[mt][nt][2] + b0, v11 = acc[mt][nt][3] + b1;
            if constexpr (sizeof(OutT) == 2) {
                *(__half2*)((__half*)C + (size_t)r * N + cc)       = __floats2half2_rn(v00, v01);
                *(__half2*)((__half*)C + (size_t)(r + 8) * N + cc) = __floats2half2_rn(v10, v11);
            } else {
                *(float2*)((float*)C + (size_t)r * N + cc)       = make_float2(v00, v01);
                *(float2*)((float*)C + (size_t)(r + 8) * N + cc) = make_float2(v10, v11);
            }
        }
    }
}

// ---------------------------------------------------------------------------
// HGEMM proj + fused NCHW scatter. Epilogue v2: tile staged TRANSPOSED
// (tile[col][p], stride 132 -> conflict-free STS, LDS.128 reads) and written
// with STG.128 (4 consecutive spatial positions; runs never straddle a batch
// since 3136 % 4 == 0 and p-base is a multiple of 4).
// ---------------------------------------------------------------------------
__global__ __launch_bounds__(128, 2) void hgemm_proj(const __half* __restrict__ A,
                                                     const __half* __restrict__ Bt,
                                                     const float* __restrict__ bias,
                                                     float* __restrict__ out) {
    constexpr int K = DIM, N = DIM;
    extern __shared__ char dsm[];
    const uint32_t sb = (smem_u32(dsm) + 1023u) & ~1023u;

    const int tid  = threadIdx.x;
    const int wid  = tid >> 5, lane = tid & 31;
    const int wm   = wid & 1;
    const int wn   = wid >> 1;

    const __half* Ap = A  + (size_t)blockIdx.y * 128 * K;
    const __half* Bp = Bt + (size_t)blockIdx.x * 128 * K;
    constexpr int NC = K >> 6;

    auto load_stage = [&](int stage, int k0) {
        const uint32_t sA = sb + stage * STAGE_B, sB = sA + 16384;
#pragma unroll
        for (int i = 0; i < 8; i++) {
            int seg = tid + 128 * i;
            int row = seg >> 3, j = seg & 7;
            uint32_t dst = (uint32_t)(row * 128 + ((j ^ (row & 7)) << 4));
            cp16(sA + dst, Ap + (size_t)row * K + k0 + j * 8);
            cp16(sB + dst, Bp + (size_t)row * K + k0 + j * 8);
        }
        asm volatile("cp.async.commit_group;" ::: "memory");
    };

    load_stage(0, 0);
    if (NC > 1) load_stage(1, 64);

    float acc[4][8][4] = {};
    const int arow = wm * 64 + (lane & 15);
    const int ac   = lane >> 4;
    const int arx  = arow & 7;
    const int brow4 = wn * 64 + ((lane >> 4) << 3) + (lane & 7);
    const int bc4   = (lane >> 3) & 1;
    const int brx4  = brow4 & 7;

#pragma unroll
    for (int c = 0; c < NC; c++) {
        if (c + 1 < NC) asm volatile("cp.async.wait_group 1;" ::: "memory");
        else            asm volatile("cp.async.wait_group 0;" ::: "memory");
        __syncthreads();
        if (c + 2 < NC) load_stage((c + 2) % 3, (c + 2) * 64);

        const uint32_t sA = sb + (c % 3) * STAGE_B, sB = sA + 16384;
#pragma unroll
        for (int ks = 0; ks < 4; ks++) {
            uint32_t af[4][4], bf[8][2];
#pragma unroll
            for (int mt = 0; mt < 4; mt++) {
                int row = arow + mt * 16;
                uint32_t addr = sA + (uint32_t)(row * 128 +
                                (((ks * 2 + ac) ^ arx) << 4));
                ldsm_x4(af[mt], addr);
            }
#pragma unroll
            for (int p = 0; p < 4; p++) {
                int row = brow4 + p * 16;
                uint32_t addr = sB + (uint32_t)(row * 128 +
                                (((ks * 2 + bc4) ^ brx4) << 4));
                uint32_t r4[4];
                ldsm_x4(r4, addr);
                bf[2 * p][0] = r4[0]; bf[2 * p][1] = r4[1];
                bf[2 * p + 1][0] = r4[2]; bf[2 * p + 1][1] = r4[3];
            }
#pragma unroll
            for (int mt = 0; mt < 4; mt++)
#pragma unroll
                for (int nt = 0; nt < 8; nt++)
                    mma16816(acc[mt][nt], af[mt], bf[nt]);
        }
    }

    // ---- fused scatter epilogue (transposed tile) ----
    __syncthreads();
    float* tile = (float*)dsm;             // tile[col][p], 128 x 132 f32
    constexpr int TSP = 132;
    const int rl0 = wm * 64 + (lane >> 2);
    const int cl0 = wn * 64 + (lane & 3) * 2;
#pragma unroll
    for (int mt = 0; mt < 4; mt++) {
#pragma unroll
        for (int nt = 0; nt < 8; nt++) {
            int rl = rl0 + mt * 16, cl = cl0 + nt * 8;
            float b0 = bias[blockIdx.x * 128 + cl];
            float b1 = bias[blockIdx.x * 128 + cl + 1];
            tile[cl * TSP + rl]           = acc[mt][nt][0] + b0;
            tile[(cl + 1) * TSP + rl]     = acc[mt][nt][1] + b1;
            tile[cl * TSP + rl + 8]       = acc[mt][nt][2] + b0;
            tile[(cl + 1) * TSP + rl + 8] = acc[mt][nt][3] + b1;
        }
    }
    __syncthreads();
    const int R0 = blockIdx.y * 128;
    const int C0 = blockIdx.x * 128;
    const int p0 = lane * 4;
    const int pg = R0 + p0;
    const int b  = pg / SPB, rem = pg % SPB;   // 4-run never straddles batch
#pragma unroll 4
    for (int dl = 0; dl < 32; dl++) {
        int c = wid * 32 + dl;
        float4 v = *(float4*)&tile[c * TSP + p0];
        *(float4*)&out[((size_t)b * DIM + C0 + c) * SPB + rem] = v;
    }
}

// ---------------------------------------------------------------------------
// Tensor-core attention — UNCHANGED from R16 (regs 126, 4 blocks/SM).
// ---------------------------------------------------------------------------
#define AW_ROWS  49
#define AW_MAT   (AW_ROWS * 80)
#define AW_BYTES (3 * AW_MAT)
#define AW_WARPS 4

__global__ __launch_bounds__(128, 4) void attn_mma(const __half* __restrict__ qkv,
                                                   __half* __restrict__ att) {
    extern __shared__ char sm[];
    const int warp = threadIdx.x >> 5, lane = threadIdx.x & 31;
    const int pairid = blockIdx.x * AW_WARPS + warp;
    const int win = pairid / HEADS, h = pairid % HEADS;
    const int wb = win >> 6, wh = (win >> 3) & 7, ww = win & 7;
    const size_t winbase = (size_t)wb * SPB + wh * 7 * 56 + ww * 7;

    char* smp = sm + warp * AW_BYTES;
    const uint32_t base = smem_u32(smp);
    const uint32_t sq = base, sk = base + AW_MAT, sv = base + 2 * AW_MAT;

    const __half* qp = qkv + winbase * QKVN + h * HD;

    for (int i = lane; i < 196; i += 32) {
        int t = i >> 2, seg = i & 3;
        int rowoff = (t / 7) * 56 + (t % 7);
        const __half* s0 = qp + (size_t)rowoff * QKVN + seg * 8;
        uint32_t d0 = (uint32_t)(t * 80 + seg * 16);
#pragma unroll
        for (int m = 0; m < 3; m++)
            cp16(base + m * AW_MAT + d0, s0 + m * DIM);
    }
    asm volatile("cp.async.commit_group;" ::: "memory");
    asm volatile("cp.async.wait_group 0;" ::: "memory");
    __syncwarp();

    const int r   = lane >> 2;
    const int cpr = lane & 3;

    uint32_t kb[7][2][2];
#pragma unroll
    for (int nt = 0; nt < 7; nt++)
#pragma unroll
        for (int ks = 0; ks < 2; ks++) {
            int row = nt * 8 + (lane & 7);
            if (row > 48) row = 48;
            uint32_t addr = sk + (uint32_t)(row * 80 +
                            (ks * 2 + ((lane >> 3) & 1)) * 16);
            ldsm_x2(kb[nt][ks], addr);
        }

    const float CSC = 0.25506153f;  // (1/sqrt(32)) * log2(e)
    const int vrow_base = lane & 15;

#pragma unroll
    for (int mt = 0; mt < 4; mt++) {
        uint32_t qa[2][4];
        {
            int row = mt * 16 + (lane & 15);
            if (row > 48) row = 48;
#pragma unroll
            for (int ks = 0; ks < 2; ks++) {
                uint32_t addr = sq + (uint32_t)(row * 80 +
                                (ks * 2 + (lane >> 4)) * 16);
                ldsm_x4(qa[ks], addr);
            }
        }
        float s[7][4] = {};
#pragma unroll
        for (int nt = 0; nt < 7; nt++) {
            mma16816(s[nt], qa[0], kb[nt][0]);
            mma16816(s[nt], qa[1], kb[nt][1]);
        }
#pragma unroll
        for (int nt = 0; nt < 7; nt++)
#pragma unroll
            for (int j = 0; j < 4; j++) s[nt][j] *= CSC;
        if (cpr != 0) { s[6][0] = s[6][1] = s[6][2] = s[6][3] = -1e30f; }
        else          { s[6][1] = s[6][3] = -1e30f; }

        float mA = -1e30f, mB = -1e30f;
#pragma unroll
        for (int nt = 0; nt < 7; nt++) {
            mA = fmaxf(mA, fmaxf(s[nt][0], s[nt][1]));
            mB = fmaxf(mB, fmaxf(s[nt][2], s[nt][3]));
        }
        mA = fmaxf(mA, __shfl_xor_sync(0xffffffffu, mA, 1));
        mA = fmaxf(mA, __shfl_xor_sync(0xffffffffu, mA, 2));
        mB = fmaxf(mB, __shfl_xor_sync(0xffffffffu, mB, 1));
        mB = fmaxf(mB, __shfl_xor_sync(0xffffffffu, mB, 2));

        float sumA = 0.f, sumB = 0.f;
#pragma unroll
        for (int nt = 0; nt < 7; nt++) {
            s[nt][0] = ex2(s[nt][0] - mA);
            s[nt][1] = ex2(s[nt][1] - mA);
            s[nt][2] = ex2(s[nt][2] - mB);
            s[nt][3] = ex2(s[nt][3] - mB);
            sumA += s[nt][0] + s[nt][1];
            sumB += s[nt][2] + s[nt][3];
        }
        sumA += __shfl_xor_sync(0xffffffffu, sumA, 1);
        sumA += __shfl_xor_sync(0xffffffffu, sumA, 2);
        sumB += __shfl_xor_sync(0xffffffffu, sumB, 1);
        sumB += __shfl_xor_sync(0xffffffffu, sumB, 2);
        const float invA = 1.0f / sumA, invB = 1.0f / sumB;

        uint32_t pa[4][4];
#pragma unroll
        for (int ks = 0; ks < 4; ks++) {
            int nt0 = 2 * ks, nt1 = 2 * ks + 1;
            pa[ks][0] = pack_h2(s[nt0][0] * invA, s[nt0][1] * invA);
            pa[ks][1] = pack_h2(s[nt0][2] * invB, s[nt0][3] * invB);
            if (nt1 < 7) {
                pa[ks][2] = pack_h2(s[nt1][0] * invA, s[nt1][1] * invA);
                pa[ks][3] = pack_h2(s[nt1][2] * invB, s[nt1][3] * invB);
            } else {
                pa[ks][2] = 0u; pa[ks][3] = 0u;
            }
        }

        float o[4][4] = {};
#pragma unroll
        for (int ks = 0; ks < 4; ks++) {
            int vrow = ks * 16 + vrow_base;
            if (vrow > 48) vrow = 48;
#pragma unroll
            for (int nd = 0; nd < 4; nd++) {
                uint32_t vbf[2];
                ldsm_x2t(vbf, sv + (uint32_t)(vrow * 80 + nd * 16));
                mma16816(o[nd], pa[ks], vbf);
            }
        }

        const int rowA = mt * 16 + r;
        const int rowB = rowA + 8;
        const size_t grA = winbase + (rowA / 7) * 56 + (rowA % 7);
        const size_t grB = winbase + (rowB / 7) * 56 + (rowB % 7);
#pragma unroll
        for (int nd = 0; nd < 4; nd++) {
            int col = h * HD + nd * 8 + cpr * 2;
            if (rowA < NTOK)
                *(__half2*)(att + grA * DIM + col) =
                    __floats2half2_rn(o[nd][0], o[nd][1]);
            if (rowB < NTOK)
                *(__half2*)(att + grB * DIM + col) =
                    __floats2half2_rn(o[nd][2], o[nd][3]);
        }
    }
}

// ---------------------------------------------------------------------------
extern "C" void kernel_launch(void* const* d_in, const int* in_sizes, int n_in,
                              void* d_out, int out_size) {
    const float* x     = (const float*)d_in[0];
    const float* Wqkv  = (const float*)d_in[1];
    const float* bqkv  = (const float*)d_in[2];
    const float* Wproj = (const float*)d_in[3];
    const float* bproj = (const float*)d_in[4];
    float* out = (float*)d_out;

    __half *xwh, *qkvh, *atth, *wt, *wtp;
    cudaGetSymbolAddress((void**)&xwh,  g_xwh);
    cudaGetSymbolAddress((void**)&qkvh, g_qkvh);
    cudaGetSymbolAddress((void**)&atth, g_atth);
    cudaGetSymbolAddress((void**)&wt,   g_wt);
    cudaGetSymbolAddress((void**)&wtp,  g_wtp);

    const int gemm_smem = 3 * STAGE_B + 1024;   // also covers 128x132 f32 tile
    cudaFuncSetAttribute((const void*)hgemm<__half, DIM>,
                         cudaFuncAttributeMaxDynamicSharedMemorySize, gemm_smem);
    cudaFuncSetAttribute((const void*)hgemm_proj,
                         cudaFuncAttributeMaxDynamicSharedMemorySize, gemm_smem);
    const int attn_smem = AW_WARPS * AW_BYTES;   // 47040 B -> 4 blocks/SM
    cudaFuncSetAttribute(attn_mma, cudaFuncAttributeMaxDynamicSharedMemorySize, attn_smem);

    // merged gather + weight transposes (one launch)
    prep<<<dim3(6, HW, BB + 2), 256>>>(x, xwh, Wqkv, wt, Wproj, wtp);
    hgemm<__half, DIM><<<dim3(QKVN / 128, ROWS / 128), 128, gemm_smem>>>(
        xwh, wt, bqkv, qkvh, ROWS, QKVN);
    attn_mma<<<NWIN * HEADS / AW_WARPS, 128, attn_smem>>>(qkvh, atth);
    hgemm_proj<<<dim3(DIM / 128, ROWS / 128), 128, gemm_smem>>>(
        atth, wtp, bproj, out);
}